// round 5
// baseline (speedup 1.0000x reference)
#include <cuda_runtime.h>
#include <math_constants.h>
#include <cstdint>

#define BCL   16
#define NPTS  4096
#define MCTR  1024
#define CIN   64
#define HID   64
#define OUTC  128
#define KNBR  64
#define NCTR  (BCL*MCTR)

// ---------------- device scratch (no allocs allowed) ----------------
__device__ float g_F1[(size_t)BCL*NPTS*HID];   // 16 MB: feat @ W1[0:64]
__device__ int   g_nbr[(size_t)NCTR*KNBR];
__device__ int   g_cnt[NCTR];

// d2 with NO fma contraction, left-assoc — must match XLA's sum((a-b)**2, -1)
__device__ __forceinline__ float d2_nofma(float dx, float dy, float dz) {
    return __fadd_rn(__fadd_rn(__fmul_rn(dx, dx), __fmul_rn(dy, dy)), __fmul_rn(dz, dz));
}

// =====================================================================
// Kernel 1: farthest point sampling. 1 block / cloud, 1024 threads,
// each thread owns 4 points in registers. Argmax ties -> lowest index.
// =====================================================================
__global__ __launch_bounds__(1024) void fps_kernel(
    const float* __restrict__ pos,
    float* __restrict__ out_centers,   // [NCTR,3]
    float* __restrict__ out_batch)     // [NCTR]
{
    const int b   = blockIdx.x;
    const int tid = threadIdx.x;
    const float* P = pos + (size_t)b * NPTS * 3;

    float px[4], py[4], pz[4], dd[4];
#pragma unroll
    for (int k = 0; k < 4; k++) {
        int j = tid + (k << 10);
        px[k] = P[3*j]; py[k] = P[3*j+1]; pz[k] = P[3*j+2];
        dd[k] = CUDART_INF_F;
    }

    __shared__ float s_cx, s_cy, s_cz;
    __shared__ float s_wd[32], s_wx[32], s_wy[32], s_wz[32];
    __shared__ int   s_wi[32];

    if (tid == 0) {
        s_cx = px[0]; s_cy = py[0]; s_cz = pz[0];
        size_t o = (size_t)b * MCTR;
        out_centers[o*3+0] = px[0];
        out_centers[o*3+1] = py[0];
        out_centers[o*3+2] = pz[0];
        out_batch[o] = (float)b;
    }
    __syncthreads();

    const int lane = tid & 31, wid = tid >> 5;

    for (int m = 1; m < MCTR; m++) {
        float cx = s_cx, cy = s_cy, cz = s_cz;
        float bd = -1.0f, bx = 0.f, by = 0.f, bz = 0.f;
        int bi = 0;
#pragma unroll
        for (int k = 0; k < 4; k++) {
            float dx = px[k] - cx, dy = py[k] - cy, dz = pz[k] - cz;
            float nd = d2_nofma(dx, dy, dz);
            dd[k] = fminf(dd[k], nd);
            // j ascends with k, so strict > keeps the lowest index on ties
            if (dd[k] > bd) {
                bd = dd[k]; bi = tid + (k << 10);
                bx = px[k]; by = py[k]; bz = pz[k];
            }
        }
        // warp reduce (max, tie -> lower idx), carrying coords
#pragma unroll
        for (int off = 16; off > 0; off >>= 1) {
            float od = __shfl_down_sync(0xFFFFFFFFu, bd, off);
            int   oi = __shfl_down_sync(0xFFFFFFFFu, bi, off);
            float ox = __shfl_down_sync(0xFFFFFFFFu, bx, off);
            float oy = __shfl_down_sync(0xFFFFFFFFu, by, off);
            float oz = __shfl_down_sync(0xFFFFFFFFu, bz, off);
            if (od > bd || (od == bd && oi < bi)) { bd = od; bi = oi; bx = ox; by = oy; bz = oz; }
        }
        if (lane == 0) { s_wd[wid] = bd; s_wi[wid] = bi; s_wx[wid] = bx; s_wy[wid] = by; s_wz[wid] = bz; }
        __syncthreads();
        if (wid == 0) {
            bd = s_wd[lane]; bi = s_wi[lane]; bx = s_wx[lane]; by = s_wy[lane]; bz = s_wz[lane];
#pragma unroll
            for (int off = 16; off > 0; off >>= 1) {
                float od = __shfl_down_sync(0xFFFFFFFFu, bd, off);
                int   oi = __shfl_down_sync(0xFFFFFFFFu, bi, off);
                float ox = __shfl_down_sync(0xFFFFFFFFu, bx, off);
                float oy = __shfl_down_sync(0xFFFFFFFFu, by, off);
                float oz = __shfl_down_sync(0xFFFFFFFFu, bz, off);
                if (od > bd || (od == bd && oi < bi)) { bd = od; bi = oi; bx = ox; by = oy; bz = oz; }
            }
            if (lane == 0) {
                s_cx = bx; s_cy = by; s_cz = bz;
                size_t o = (size_t)b * MCTR + m;
                out_centers[o*3+0] = bx;
                out_centers[o*3+1] = by;
                out_centers[o*3+2] = bz;
                out_batch[o] = (float)b;
            }
        }
        __syncthreads();
    }
}

// =====================================================================
// Kernel 2: F1 = feat @ W1[0:64]  (per-point, center-independent part)
// =====================================================================
__global__ __launch_bounds__(64) void f1_kernel(
    const float* __restrict__ feat, const float* __restrict__ W1)
{
    __shared__ float sf[64][65];
    __shared__ float sw[64][64];
    const int p0  = blockIdx.x * 64;
    const int tid = threadIdx.x;

    for (int i = tid; i < 4096; i += 64) sw[i >> 6][i & 63] = W1[i];      // rows 0..63 of W1
    for (int i = tid; i < 4096; i += 64) {
        int p = i >> 6, c = i & 63;
        sf[p][c] = feat[(size_t)(p0 + p) * CIN + c];
    }
    __syncthreads();

    const int c = tid;
    for (int p = 0; p < 64; p += 4) {
        float a0 = 0.f, a1 = 0.f, a2 = 0.f, a3 = 0.f;
#pragma unroll
        for (int k = 0; k < 64; k++) {
            float w = sw[k][c];
            a0 += sf[p+0][k] * w;
            a1 += sf[p+1][k] * w;
            a2 += sf[p+2][k] * w;
            a3 += sf[p+3][k] * w;
        }
        g_F1[(size_t)(p0+p+0)*HID + c] = a0;
        g_F1[(size_t)(p0+p+1)*HID + c] = a1;
        g_F1[(size_t)(p0+p+2)*HID + c] = a2;
        g_F1[(size_t)(p0+p+3)*HID + c] = a3;
    }
}

// =====================================================================
// Kernel 3: exact K-nearest-in-ball selection per center.
// Radix-select rank-64 on float bits, boundary ties -> lowest indices.
// =====================================================================
__global__ __launch_bounds__(128) void select_kernel(
    const float* __restrict__ pos, const float* __restrict__ centers)
{
    const int cid = blockIdx.x;
    const int b   = cid >> 10;
    const int tid = threadIdx.x;
    const float* P = pos + (size_t)b * NPTS * 3;

    __shared__ unsigned u[NPTS];
    __shared__ int hist[256];
    __shared__ int s_cnt, s_pos, s_bin, s_klt, s_eqn;
    __shared__ int s_eq[64];

    const float cx = centers[(size_t)cid*3+0];
    const float cy = centers[(size_t)cid*3+1];
    const float cz = centers[(size_t)cid*3+2];
    const float R2 = (float)(0.2 * 0.2);

    if (tid == 0) s_cnt = 0;
    __syncthreads();

    int lv = 0;
    for (int j = tid; j < NPTS; j += 128) {
        float dx = cx - P[3*j], dy = cy - P[3*j+1], dz = cz - P[3*j+2];
        float d2 = d2_nofma(dx, dy, dz);
        unsigned v = 0xFFFFFFFFu;
        if (d2 < R2) { v = __float_as_uint(d2); lv++; }
        u[j] = v;
    }
    if (lv) atomicAdd(&s_cnt, lv);
    __syncthreads();
    const int cnt = s_cnt;

    if (cnt <= KNBR) {                       // take every valid neighbor
        if (tid == 0) s_pos = 0;
        __syncthreads();
        for (int j = tid; j < NPTS; j += 128)
            if (u[j] != 0xFFFFFFFFu) {
                int p = atomicAdd(&s_pos, 1);
                g_nbr[(size_t)cid*KNBR + p] = j;
            }
        __syncthreads();
        if (tid == 0) {
            for (int p = cnt; p < KNBR; p++) g_nbr[(size_t)cid*KNBR + p] = 0; // safe dummies
            g_cnt[cid] = cnt;
        }
        return;
    }

    // radix select: find the 64th smallest uint among valid entries
    unsigned pref = 0; int k = KNBR;
    for (int sh = 24; sh >= 0; sh -= 8) {
        for (int i = tid; i < 256; i += 128) hist[i] = 0;
        __syncthreads();
        unsigned hm = (sh == 24) ? 0u : (0xFFFFFFFFu << (sh + 8));
        for (int j = tid; j < NPTS; j += 128) {
            unsigned v = u[j];
            if (v != 0xFFFFFFFFu && (v & hm) == pref)
                atomicAdd(&hist[(v >> sh) & 255], 1);
        }
        __syncthreads();
        if (tid == 0) {
            int c = 0;
            for (int bin = 0; bin < 256; bin++) {
                int h = hist[bin];
                if (c + h >= k) { s_bin = bin; s_klt = k - c; break; }
                c += h;
            }
        }
        __syncthreads();
        pref |= ((unsigned)s_bin) << sh;
        k = s_klt;
        __syncthreads();
    }
    const unsigned T = pref;   // exact 64th smallest value; k = rank within equals

    if (tid == 0) { s_pos = 0; s_eqn = 0; }
    __syncthreads();
    for (int j = tid; j < NPTS; j += 128) {
        unsigned v = u[j];
        if (v < T) {
            int p = atomicAdd(&s_pos, 1);
            g_nbr[(size_t)cid*KNBR + p] = j;
        } else if (v == T) {
            int e = atomicAdd(&s_eqn, 1);
            if (e < 64) s_eq[e] = j;
        }
    }
    __syncthreads();
    if (tid == 0) {
        int base = s_pos;                 // = 64 - k
        int ne = s_eqn < 64 ? s_eqn : 64;
        for (int a = 1; a < ne; a++) {    // ascending index (stable-top_k tie order)
            int key = s_eq[a], t2 = a - 1;
            while (t2 >= 0 && s_eq[t2] > key) { s_eq[t2+1] = s_eq[t2]; t2--; }
            s_eq[t2+1] = key;
        }
        for (int a = 0; a < k; a++) g_nbr[(size_t)cid*KNBR + base + a] = s_eq[a];
        g_cnt[cid] = KNBR;
    }
}

// =====================================================================
// Kernel 4: fused MLP (layers 1..3) + masked max-pool. 1 block / center.
// W3 is read from global (L2-resident) to keep static smem < 48KB so
// kernel_launch stays launch-only (no attribute calls during capture).
// =====================================================================
struct MlpSmem {
    float h[64][68];        // h1, then reused for h2
    float W2[64][64];
    float cmax[16][128];
    float dp[64][3];
    float w1p[3][64];
    float b1[64], b2[64], b3[128];
    int   idx[64];
    int   cnt;
};          // ~44.8 KB static

__global__ __launch_bounds__(128) void mlp_kernel(
    const float* __restrict__ pos, const float* __restrict__ centers,
    const float* __restrict__ W1, const float* __restrict__ b1,
    const float* __restrict__ W2, const float* __restrict__ b2,
    const float* __restrict__ W3, const float* __restrict__ b3,
    float* __restrict__ out)
{
    __shared__ MlpSmem S;

    const int cid = blockIdx.x;
    const int b   = cid >> 10;
    const int tid = threadIdx.x;

    // ---- load weights / biases / neighbor metadata ----
    for (int i = tid; i < 1024; i += 128) ((float4*)S.W2)[i] = ((const float4*)W2)[i];
    for (int i = tid; i < 192;  i += 128) ((float*)S.w1p)[i] = W1[4096 + i];   // rows 64..66
    if (tid < 64)  { S.b1[tid] = b1[tid]; S.b2[tid] = b2[tid]; }
    S.b3[tid] = b3[tid];
    if (tid == 0) S.cnt = g_cnt[cid];

    const float cx = centers[(size_t)cid*3+0];
    const float cy = centers[(size_t)cid*3+1];
    const float cz = centers[(size_t)cid*3+2];
    if (tid < 64) {
        int jl = g_nbr[(size_t)cid*KNBR + tid];
        S.idx[tid] = jl;
        const float* Pp = pos + ((size_t)b*NPTS + jl) * 3;
        S.dp[tid][0] = Pp[0] - cx;
        S.dp[tid][1] = Pp[1] - cy;
        S.dp[tid][2] = Pp[2] - cz;
    }
    __syncthreads();
    const int cnt = S.cnt;

    // ---- h1 = relu(F1[j] + dpos @ W1pos + b1) ----
    const size_t fbase = (size_t)b * NPTS;
    for (int i = tid; i < 4096; i += 128) {
        int n = i >> 6, c = i & 63;
        float v = g_F1[(fbase + S.idx[n]) * HID + c];
        v += S.dp[n][0]*S.w1p[0][c] + S.dp[n][1]*S.w1p[1][c] + S.dp[n][2]*S.w1p[2][c] + S.b1[c];
        S.h[n][c] = fmaxf(v, 0.0f);
    }
    __syncthreads();

    // ---- h2 = relu(h1 @ W2 + b2): 64x64x64, 4x8 register tiles ----
    const int rg = tid >> 3, cg = tid & 7;
    const int r0 = rg * 4,  c0 = cg * 8;
    float acc[4][8];
#pragma unroll
    for (int r = 0; r < 4; r++)
#pragma unroll
        for (int c = 0; c < 8; c++) acc[r][c] = S.b2[c0 + c];
#pragma unroll 8
    for (int k = 0; k < 64; k++) {
        float a0 = S.h[r0+0][k], a1 = S.h[r0+1][k], a2 = S.h[r0+2][k], a3 = S.h[r0+3][k];
#pragma unroll
        for (int c = 0; c < 8; c++) {
            float w = S.W2[k][c0 + c];
            acc[0][c] += a0 * w; acc[1][c] += a1 * w;
            acc[2][c] += a2 * w; acc[3][c] += a3 * w;
        }
    }
    __syncthreads();   // all h1 reads done before overwrite
#pragma unroll
    for (int r = 0; r < 4; r++)
#pragma unroll
        for (int c = 0; c < 8; c++)
            S.h[r0 + r][c0 + c] = fmaxf(acc[r][c], 0.0f);
    __syncthreads();

    // ---- h3 = relu(h2 @ W3 + b3): 64x128x64, W3 streamed from global ----
    const int c1 = cg * 16;
    float acc3[4][16];
#pragma unroll
    for (int r = 0; r < 4; r++)
#pragma unroll
        for (int c = 0; c < 16; c++) acc3[r][c] = S.b3[c1 + c];
#pragma unroll 4
    for (int k = 0; k < 64; k++) {
        float a0 = S.h[r0+0][k], a1 = S.h[r0+1][k], a2 = S.h[r0+2][k], a3 = S.h[r0+3][k];
        const float4* wrow = (const float4*)(W3 + (size_t)k * OUTC + c1);
#pragma unroll
        for (int q = 0; q < 4; q++) {
            float4 w4 = __ldg(&wrow[q]);
            float w;
            w = w4.x; acc3[0][4*q+0] += a0*w; acc3[1][4*q+0] += a1*w; acc3[2][4*q+0] += a2*w; acc3[3][4*q+0] += a3*w;
            w = w4.y; acc3[0][4*q+1] += a0*w; acc3[1][4*q+1] += a1*w; acc3[2][4*q+1] += a2*w; acc3[3][4*q+1] += a3*w;
            w = w4.z; acc3[0][4*q+2] += a0*w; acc3[1][4*q+2] += a1*w; acc3[2][4*q+2] += a2*w; acc3[3][4*q+2] += a3*w;
            w = w4.w; acc3[0][4*q+3] += a0*w; acc3[1][4*q+3] += a1*w; acc3[2][4*q+3] += a2*w; acc3[3][4*q+3] += a3*w;
        }
    }
    float cm[16];
#pragma unroll
    for (int c = 0; c < 16; c++) cm[c] = -CUDART_INF_F;
#pragma unroll
    for (int r = 0; r < 4; r++) {
        if (r0 + r < cnt) {
#pragma unroll
            for (int c = 0; c < 16; c++)
                cm[c] = fmaxf(cm[c], fmaxf(acc3[r][c], 0.0f));
        }
    }
#pragma unroll
    for (int c = 0; c < 16; c++) S.cmax[rg][c1 + c] = cm[c];
    __syncthreads();

    // ---- final reduction over the 16 row-groups ----
    float v = -CUDART_INF_F;
#pragma unroll
    for (int g = 0; g < 16; g++) v = fmaxf(v, S.cmax[g][tid]);
    out[(size_t)cid * OUTC + tid] = v;
}

// =====================================================================
extern "C" void kernel_launch(void* const* d_in, const int* in_sizes, int n_in,
                              void* d_out, int out_size)
{
    // Identify inputs by element count (robust to num_samples being or not
    // being materialized as a device array, and to ordering changes).
    const float *xyz = nullptr, *point = nullptr;
    const float *W1 = nullptr, *b1 = nullptr, *W2 = nullptr, *b2 = nullptr;
    const float *W3 = nullptr, *b3 = nullptr;
    for (int i = 0; i < n_in; i++) {
        switch (in_sizes[i]) {
            case 4194304: xyz   = (const float*)d_in[i]; break;  // 65536*64
            case 196608:  point = (const float*)d_in[i]; break;  // 65536*3
            case 4288:    W1    = (const float*)d_in[i]; break;  // 67*64
            case 4096:    W2    = (const float*)d_in[i]; break;  // 64*64
            case 8192:    W3    = (const float*)d_in[i]; break;  // 64*128
            case 128:     b3    = (const float*)d_in[i]; break;
            case 64:      if (!b1) b1 = (const float*)d_in[i];
                          else     b2 = (const float*)d_in[i];   break;
            default: break;  // batch (65536), num_samples (1)
        }
    }

    float* out      = (float*)d_out;
    float* cenout   = out + (size_t)NCTR * OUTC;
    float* batchout = cenout + (size_t)NCTR * 3;

    fps_kernel<<<BCL, 1024>>>(point, cenout, batchout);
    f1_kernel<<<(BCL * NPTS) / 64, 64>>>(xyz, W1);
    select_kernel<<<NCTR, 128>>>(point, cenout);
    mlp_kernel<<<NCTR, 128>>>(point, cenout, W1, b1, W2, b2, W3, b3, out);
}

// round 8
// speedup vs baseline: 1.8521x; 1.8521x over previous
#include <cuda_runtime.h>
#include <math_constants.h>
#include <cstdint>

#define BCL   16
#define NPTS  4096
#define MCTR  1024
#define CIN   64
#define HID   64
#define OUTC  128
#define KNBR  64
#define NCTR  (BCL*MCTR)

typedef unsigned long long ull;

// ---------------- device scratch (no allocs allowed) ----------------
__device__ float g_F1[(size_t)BCL*NPTS*HID];   // 16 MB: feat @ W1[0:64]
__device__ int   g_nbr[(size_t)NCTR*KNBR];
__device__ int   g_cnt[NCTR];

// d2 with NO fma contraction, left-assoc — must match XLA's sum((a-b)**2, -1)
__device__ __forceinline__ float d2_nofma(float dx, float dy, float dz) {
    return __fadd_rn(__fadd_rn(__fmul_rn(dx, dx), __fmul_rn(dy, dy)), __fmul_rn(dz, dz));
}

// ---------------- packed f32x2 helpers (sm_103a) ----------------
__device__ __forceinline__ ull pk2(float lo, float hi) {
    ull r;
    asm("mov.b64 %0, {%1, %2};" : "=l"(r)
        : "r"(__float_as_uint(lo)), "r"(__float_as_uint(hi)));
    return r;
}
__device__ __forceinline__ float2 upk2(ull v) {
    unsigned lo, hi;
    asm("mov.b64 {%0, %1}, %2;" : "=r"(lo), "=r"(hi) : "l"(v));
    return make_float2(__uint_as_float(lo), __uint_as_float(hi));
}
__device__ __forceinline__ ull mul2(ull a, ull b) {
    ull r; asm("mul.rn.f32x2 %0, %1, %2;" : "=l"(r) : "l"(a), "l"(b)); return r;
}
__device__ __forceinline__ ull add2(ull a, ull b) {
    ull r; asm("add.rn.f32x2 %0, %1, %2;" : "=l"(r) : "l"(a), "l"(b)); return r;
}
__device__ __forceinline__ void fma2(ull& d, ull a, ull b) {
    asm("fma.rn.f32x2 %0, %1, %2, %0;" : "+l"(d) : "l"(a), "l"(b));
}

// =====================================================================
// Kernel 1: FPS. 1 block/cloud, 128 threads x 32 pts in registers.
// Packed f32x2 distance math (elementwise identical to scalar .rn ops),
// u64 (d2bits<<32 | ~idx) argmax keys, ONE barrier per iteration.
// =====================================================================
__global__ __launch_bounds__(128) void fps_kernel(
    const float* __restrict__ pos,
    float* __restrict__ out_centers,   // [NCTR,3]
    float* __restrict__ out_batch)     // [NCTR]
{
    const int b   = blockIdx.x;
    const int tid = threadIdx.x;
    const float* P = pos + (size_t)b * NPTS * 3;

    ull pxp[16], pyp[16], pzp[16];
    float dd[32];
#pragma unroll
    for (int q = 0; q < 16; q++) {
        int jA = tid + (q << 8);      // tid + 256q
        int jB = jA + 128;
        pxp[q] = pk2(P[3*jA],   P[3*jB]);
        pyp[q] = pk2(P[3*jA+1], P[3*jB+1]);
        pzp[q] = pk2(P[3*jA+2], P[3*jB+2]);
    }
#pragma unroll
    for (int i = 0; i < 32; i++) dd[i] = CUDART_INF_F;

    __shared__ ull s_wk[2][4];
    const int lane = tid & 31, wid = tid >> 5;

    int jwin = 0;
    for (int m = 0; m < MCTR; m++) {
        // all threads load current center (L1-resident, broadcast)
        float cx = P[3*jwin], cy = P[3*jwin+1], cz = P[3*jwin+2];
        if (tid == 0) {
            size_t o = (size_t)b * MCTR + m;
            out_centers[o*3+0] = cx;
            out_centers[o*3+1] = cy;
            out_centers[o*3+2] = cz;
            out_batch[o] = (float)b;
        }
        if (m == MCTR - 1) break;

        const ull ncx = pk2(-cx, -cx), ncy = pk2(-cy, -cy), ncz = pk2(-cz, -cz);
        float bd = -1.0f; int bj = 0;
#pragma unroll
        for (int q = 0; q < 16; q++) {
            ull dx = add2(pxp[q], ncx);            // == px - cx (exact)
            ull dy = add2(pyp[q], ncy);
            ull dz = add2(pzp[q], ncz);
            ull d2p = add2(add2(mul2(dx, dx), mul2(dy, dy)), mul2(dz, dz));
            float2 d = upk2(d2p);
            float nA = fminf(dd[2*q],   d.x);
            float nB = fminf(dd[2*q+1], d.y);
            dd[2*q] = nA; dd[2*q+1] = nB;
            // ascending j per thread, strict > keeps lowest index on ties
            if (nA > bd) { bd = nA; bj = tid + (q << 8); }
            if (nB > bd) { bd = nB; bj = tid + (q << 8) + 128; }
        }
        // key: larger d2 wins; equal d2 -> larger ~j = smaller j wins
        ull key = ((ull)__float_as_uint(bd) << 32) | (ull)(0xFFFFFFFFu - (unsigned)bj);
#pragma unroll
        for (int off = 16; off; off >>= 1) {
            ull ok = __shfl_down_sync(0xFFFFFFFFu, key, off);
            if (ok > key) key = ok;
        }
        if (lane == 0) s_wk[m & 1][wid] = key;
        __syncthreads();
        ull k0 = s_wk[m & 1][0], k1 = s_wk[m & 1][1];
        ull k2 = s_wk[m & 1][2], k3 = s_wk[m & 1][3];
        if (k1 > k0) k0 = k1;
        if (k3 > k2) k2 = k3;
        if (k2 > k0) k0 = k2;
        jwin = (int)(0xFFFFFFFFu - (unsigned)(k0 & 0xFFFFFFFFu));
    }
}

// =====================================================================
// Kernel 2: F1 = feat @ W1[0:64]  (per-point, center-independent part)
// =====================================================================
__global__ __launch_bounds__(64) void f1_kernel(
    const float* __restrict__ feat, const float* __restrict__ W1)
{
    __shared__ float sf[64][65];
    __shared__ float sw[64][64];
    const int p0  = blockIdx.x * 64;
    const int tid = threadIdx.x;

    for (int i = tid; i < 4096; i += 64) sw[i >> 6][i & 63] = W1[i];
    for (int i = tid; i < 4096; i += 64) {
        int p = i >> 6, c = i & 63;
        sf[p][c] = feat[(size_t)(p0 + p) * CIN + c];
    }
    __syncthreads();

    const int c = tid;
    for (int p = 0; p < 64; p += 4) {
        float a0 = 0.f, a1 = 0.f, a2 = 0.f, a3 = 0.f;
#pragma unroll
        for (int k = 0; k < 64; k++) {
            float w = sw[k][c];
            a0 += sf[p+0][k] * w;
            a1 += sf[p+1][k] * w;
            a2 += sf[p+2][k] * w;
            a3 += sf[p+3][k] * w;
        }
        g_F1[(size_t)(p0+p+0)*HID + c] = a0;
        g_F1[(size_t)(p0+p+1)*HID + c] = a1;
        g_F1[(size_t)(p0+p+2)*HID + c] = a2;
        g_F1[(size_t)(p0+p+3)*HID + c] = a3;
    }
}

// =====================================================================
// Kernel 3: exact K-nearest-in-ball selection per center (unchanged).
// =====================================================================
__global__ __launch_bounds__(128) void select_kernel(
    const float* __restrict__ pos, const float* __restrict__ centers)
{
    const int cid = blockIdx.x;
    const int b   = cid >> 10;
    const int tid = threadIdx.x;
    const float* P = pos + (size_t)b * NPTS * 3;

    __shared__ unsigned u[NPTS];
    __shared__ int hist[256];
    __shared__ int s_cnt, s_pos, s_bin, s_klt, s_eqn;
    __shared__ int s_eq[64];

    const float cx = centers[(size_t)cid*3+0];
    const float cy = centers[(size_t)cid*3+1];
    const float cz = centers[(size_t)cid*3+2];
    const float R2 = (float)(0.2 * 0.2);

    if (tid == 0) s_cnt = 0;
    __syncthreads();

    int lv = 0;
    for (int j = tid; j < NPTS; j += 128) {
        float dx = cx - P[3*j], dy = cy - P[3*j+1], dz = cz - P[3*j+2];
        float d2 = d2_nofma(dx, dy, dz);
        unsigned v = 0xFFFFFFFFu;
        if (d2 < R2) { v = __float_as_uint(d2); lv++; }
        u[j] = v;
    }
    if (lv) atomicAdd(&s_cnt, lv);
    __syncthreads();
    const int cnt = s_cnt;

    if (cnt <= KNBR) {
        if (tid == 0) s_pos = 0;
        __syncthreads();
        for (int j = tid; j < NPTS; j += 128)
            if (u[j] != 0xFFFFFFFFu) {
                int p = atomicAdd(&s_pos, 1);
                g_nbr[(size_t)cid*KNBR + p] = j;
            }
        __syncthreads();
        if (tid == 0) {
            for (int p = cnt; p < KNBR; p++) g_nbr[(size_t)cid*KNBR + p] = 0;
            g_cnt[cid] = cnt;
        }
        return;
    }

    unsigned pref = 0; int k = KNBR;
    for (int sh = 24; sh >= 0; sh -= 8) {
        for (int i = tid; i < 256; i += 128) hist[i] = 0;
        __syncthreads();
        unsigned hm = (sh == 24) ? 0u : (0xFFFFFFFFu << (sh + 8));
        for (int j = tid; j < NPTS; j += 128) {
            unsigned v = u[j];
            if (v != 0xFFFFFFFFu && (v & hm) == pref)
                atomicAdd(&hist[(v >> sh) & 255], 1);
        }
        __syncthreads();
        if (tid == 0) {
            int c = 0;
            for (int bin = 0; bin < 256; bin++) {
                int h = hist[bin];
                if (c + h >= k) { s_bin = bin; s_klt = k - c; break; }
                c += h;
            }
        }
        __syncthreads();
        pref |= ((unsigned)s_bin) << sh;
        k = s_klt;
        __syncthreads();
    }
    const unsigned T = pref;

    if (tid == 0) { s_pos = 0; s_eqn = 0; }
    __syncthreads();
    for (int j = tid; j < NPTS; j += 128) {
        unsigned v = u[j];
        if (v < T) {
            int p = atomicAdd(&s_pos, 1);
            g_nbr[(size_t)cid*KNBR + p] = j;
        } else if (v == T) {
            int e = atomicAdd(&s_eqn, 1);
            if (e < 64) s_eq[e] = j;
        }
    }
    __syncthreads();
    if (tid == 0) {
        int base = s_pos;
        int ne = s_eqn < 64 ? s_eqn : 64;
        for (int a = 1; a < ne; a++) {
            int key = s_eq[a], t2 = a - 1;
            while (t2 >= 0 && s_eq[t2] > key) { s_eq[t2+1] = s_eq[t2]; t2--; }
            s_eq[t2+1] = key;
        }
        for (int a = 0; a < k; a++) g_nbr[(size_t)cid*KNBR + base + a] = s_eq[a];
        g_cnt[cid] = KNBR;
    }
}

// =====================================================================
// Kernel 4: fused MLP + masked max. 2 centers/block, 128 threads.
// h stored k-major (transposed) -> LDS.128 a-vectors; weights LDG.128;
// 8x8 register tiles with packed f32x2 FFMA2 accumulators.
// =====================================================================
struct __align__(16) Mlp2Smem {
    float  ht[64][132];     // transposed activations (k-major), 33792 B
    float  cmax[16][132];   // per-rowgroup column maxima, 8448 B
    float4 wb1[64];         // (W1pos0, W1pos1, W1pos2, b1) per output ch
    float  b2[64];
    float  b3[128];
    int    cnt[2];
};                          // ~44 KB static

__global__ __launch_bounds__(128) void mlp2_kernel(
    const float* __restrict__ pos, const float* __restrict__ centers,
    const float* __restrict__ W1, const float* __restrict__ b1,
    const float* __restrict__ W2, const float* __restrict__ b2,
    const float* __restrict__ W3, const float* __restrict__ b3,
    float* __restrict__ out)
{
    __shared__ Mlp2Smem S;

    const int c0  = blockIdx.x * 2;       // first of pair; pairs never cross clouds
    const int b   = c0 >> 10;
    const int tid = threadIdx.x;

    // ---- stage weights/biases ----
    if (tid < 64) {
        S.wb1[tid] = make_float4(W1[4096 + tid], W1[4160 + tid], W1[4224 + tid], b1[tid]);
        S.b2[tid]  = b2[tid];
    }
    S.b3[tid] = b3[tid];
    if (tid < 2) S.cnt[tid] = g_cnt[c0 + tid];

    // ---- per-thread neighbor meta (n = tid, 128 neighbors = 2 centers) ----
    const int n      = tid;
    const int center = n >> 6;
    const int jl     = g_nbr[(size_t)c0 * KNBR + n];
    const float* Pp  = pos + ((size_t)b * NPTS + jl) * 3;
    const float* Cc  = centers + (size_t)(c0 + center) * 3;
    const float dp0 = Pp[0] - Cc[0];
    const float dp1 = Pp[1] - Cc[1];
    const float dp2 = Pp[2] - Cc[2];
    __syncthreads();

    // ---- h1 = relu(F1[j] + dpos @ W1pos + b1), written k-major ----
    {
        const float4* F1p = (const float4*)&g_F1[((size_t)b * NPTS + jl) * HID];
#pragma unroll
        for (int q = 0; q < 16; q++) {
            float4 f = __ldg(F1p + q);
#pragma unroll
            for (int e = 0; e < 4; e++) {
                int k = 4*q + e;
                float4 w = S.wb1[k];                       // broadcast LDS.128
                float fe = (e == 0) ? f.x : (e == 1) ? f.y : (e == 2) ? f.z : f.w;
                float v  = fe + dp0*w.x + dp1*w.y + dp2*w.z + w.w;
                S.ht[k][n] = fmaxf(v, 0.0f);
            }
        }
    }
    __syncthreads();

    const int rg = tid >> 3, cg = tid & 7;
    const int r0 = rg * 8, cbase = cg * 8;

    // ---- h2 = relu(h1 @ W2 + b2): 128x64x64, 8x8 tiles, FFMA2 ----
    ull acc[8][4];
    {
        ull binit[4];
#pragma unroll
        for (int p = 0; p < 4; p++) binit[p] = *(const ull*)&S.b2[cbase + 2*p];
#pragma unroll
        for (int r = 0; r < 8; r++)
#pragma unroll
            for (int p = 0; p < 4; p++) acc[r][p] = binit[p];
    }
#pragma unroll 4
    for (int k = 0; k < 64; k++) {
        float4 a0 = *(const float4*)&S.ht[k][r0];
        float4 a1 = *(const float4*)&S.ht[k][r0 + 4];
        ull aa[8];
        aa[0]=pk2(a0.x,a0.x); aa[1]=pk2(a0.y,a0.y); aa[2]=pk2(a0.z,a0.z); aa[3]=pk2(a0.w,a0.w);
        aa[4]=pk2(a1.x,a1.x); aa[5]=pk2(a1.y,a1.y); aa[6]=pk2(a1.z,a1.z); aa[7]=pk2(a1.w,a1.w);
        const float4* wr = (const float4*)(W2 + (size_t)k * 64 + cbase);
        float4 w0 = __ldg(wr), w1 = __ldg(wr + 1);
        ull wp[4];
        wp[0]=pk2(w0.x,w0.y); wp[1]=pk2(w0.z,w0.w); wp[2]=pk2(w1.x,w1.y); wp[3]=pk2(w1.z,w1.w);
#pragma unroll
        for (int r = 0; r < 8; r++)
#pragma unroll
            for (int p = 0; p < 4; p++) fma2(acc[r][p], aa[r], wp[p]);
    }
    __syncthreads();   // all ht reads done before overwrite

    // relu + write back transposed (rows <-> cols) so h3 reads k-major again
#pragma unroll
    for (int r = 0; r < 8; r++)
#pragma unroll
        for (int p = 0; p < 4; p++) {
            float2 v = upk2(acc[r][p]);
            S.ht[cbase + 2*p    ][r0 + r] = fmaxf(v.x, 0.0f);
            S.ht[cbase + 2*p + 1][r0 + r] = fmaxf(v.y, 0.0f);
        }
    __syncthreads();

    // ---- h3 = relu(h2 @ W3 + b3): 128x128x64 in two 64-col halves ----
    const int cn = S.cnt[rg >> 3];     // rows of this rg all belong to one center
#pragma unroll
    for (int half = 0; half < 2; half++) {
        ull acc3[8][4];
        {
            ull binit[4];
#pragma unroll
            for (int p = 0; p < 4; p++)
                binit[p] = *(const ull*)&S.b3[half*64 + cbase + 2*p];
#pragma unroll
            for (int r = 0; r < 8; r++)
#pragma unroll
                for (int p = 0; p < 4; p++) acc3[r][p] = binit[p];
        }
#pragma unroll 4
        for (int k = 0; k < 64; k++) {
            float4 a0 = *(const float4*)&S.ht[k][r0];
            float4 a1 = *(const float4*)&S.ht[k][r0 + 4];
            ull aa[8];
            aa[0]=pk2(a0.x,a0.x); aa[1]=pk2(a0.y,a0.y); aa[2]=pk2(a0.z,a0.z); aa[3]=pk2(a0.w,a0.w);
            aa[4]=pk2(a1.x,a1.x); aa[5]=pk2(a1.y,a1.y); aa[6]=pk2(a1.z,a1.z); aa[7]=pk2(a1.w,a1.w);
            const float4* wr = (const float4*)(W3 + (size_t)k * OUTC + half*64 + cbase);
            float4 w0 = __ldg(wr), w1 = __ldg(wr + 1);
            ull wp[4];
            wp[0]=pk2(w0.x,w0.y); wp[1]=pk2(w0.z,w0.w); wp[2]=pk2(w1.x,w1.y); wp[3]=pk2(w1.z,w1.w);
#pragma unroll
            for (int r = 0; r < 8; r++)
#pragma unroll
                for (int p = 0; p < 4; p++) fma2(acc3[r][p], aa[r], wp[p]);
        }
        // masked relu-max over this thread's 8 rows
        float cm[8];
#pragma unroll
        for (int c = 0; c < 8; c++) cm[c] = -CUDART_INF_F;
#pragma unroll
        for (int r = 0; r < 8; r++) {
            if (((r0 + r) & 63) < cn) {
#pragma unroll
                for (int p = 0; p < 4; p++) {
                    float2 v = upk2(acc3[r][p]);
                    cm[2*p]     = fmaxf(cm[2*p],     fmaxf(v.x, 0.0f));
                    cm[2*p + 1] = fmaxf(cm[2*p + 1], fmaxf(v.y, 0.0f));
                }
            }
        }
#pragma unroll
        for (int c = 0; c < 8; c++) S.cmax[rg][half*64 + cbase + c] = cm[c];
    }
    __syncthreads();

    // ---- final per-center reduction over rowgroups ----
    float v0 = -CUDART_INF_F, v1 = -CUDART_INF_F;
#pragma unroll
    for (int g = 0; g < 8; g++) {
        v0 = fmaxf(v0, S.cmax[g][tid]);
        v1 = fmaxf(v1, S.cmax[8 + g][tid]);
    }
    out[(size_t)c0 * OUTC + tid]       = v0;
    out[(size_t)(c0 + 1) * OUTC + tid] = v1;
}

// =====================================================================
extern "C" void kernel_launch(void* const* d_in, const int* in_sizes, int n_in,
                              void* d_out, int out_size)
{
    const float *xyz = nullptr, *point = nullptr;
    const float *W1 = nullptr, *b1 = nullptr, *W2 = nullptr, *b2 = nullptr;
    const float *W3 = nullptr, *b3 = nullptr;
    for (int i = 0; i < n_in; i++) {
        switch (in_sizes[i]) {
            case 4194304: xyz   = (const float*)d_in[i]; break;  // 65536*64
            case 196608:  point = (const float*)d_in[i]; break;  // 65536*3
            case 4288:    W1    = (const float*)d_in[i]; break;  // 67*64
            case 4096:    W2    = (const float*)d_in[i]; break;  // 64*64
            case 8192:    W3    = (const float*)d_in[i]; break;  // 64*128
            case 128:     b3    = (const float*)d_in[i]; break;
            case 64:      if (!b1) b1 = (const float*)d_in[i];
                          else     b2 = (const float*)d_in[i];   break;
            default: break;  // batch (65536), num_samples (1)
        }
    }

    float* out      = (float*)d_out;
    float* cenout   = out + (size_t)NCTR * OUTC;
    float* batchout = cenout + (size_t)NCTR * 3;

    fps_kernel<<<BCL, 128>>>(point, cenout, batchout);
    f1_kernel<<<(BCL * NPTS) / 64, 64>>>(xyz, W1);
    select_kernel<<<NCTR, 128>>>(point, cenout);
    mlp2_kernel<<<NCTR / 2, 128>>>(point, cenout, W1, b1, W2, b2, W3, b3, out);
}

// round 9
// speedup vs baseline: 1.9271x; 1.0405x over previous
#include <cuda_runtime.h>
#include <math_constants.h>
#include <cstdint>

#define BCL   16
#define NPTS  4096
#define MCTR  1024
#define CIN   64
#define HID   64
#define OUTC  128
#define KNBR  64
#define NCTR  (BCL*MCTR)

typedef unsigned long long ull;

// ---------------- device scratch (no allocs allowed) ----------------
__device__ float g_F1[(size_t)BCL*NPTS*HID];   // 16 MB: feat @ W1[0:64]
__device__ int   g_nbr[(size_t)NCTR*KNBR];
__device__ int   g_cnt[NCTR];

// d2 with NO fma contraction, left-assoc — must match XLA's sum((a-b)**2, -1)
__device__ __forceinline__ float d2_nofma(float dx, float dy, float dz) {
    return __fadd_rn(__fadd_rn(__fmul_rn(dx, dx), __fmul_rn(dy, dy)), __fmul_rn(dz, dz));
}

// ---------------- packed f32x2 helpers (sm_103a) ----------------
__device__ __forceinline__ ull pk2(float lo, float hi) {
    ull r;
    asm("mov.b64 %0, {%1, %2};" : "=l"(r)
        : "r"(__float_as_uint(lo)), "r"(__float_as_uint(hi)));
    return r;
}
__device__ __forceinline__ float2 upk2(ull v) {
    unsigned lo, hi;
    asm("mov.b64 {%0, %1}, %2;" : "=r"(lo), "=r"(hi) : "l"(v));
    return make_float2(__uint_as_float(lo), __uint_as_float(hi));
}
__device__ __forceinline__ ull mul2(ull a, ull b) {
    ull r; asm("mul.rn.f32x2 %0, %1, %2;" : "=l"(r) : "l"(a), "l"(b)); return r;
}
__device__ __forceinline__ ull add2(ull a, ull b) {
    ull r; asm("add.rn.f32x2 %0, %1, %2;" : "=l"(r) : "l"(a), "l"(b)); return r;
}
__device__ __forceinline__ void fma2(ull& d, ull a, ull b) {
    asm("fma.rn.f32x2 %0, %1, %2, %0;" : "+l"(d) : "l"(a), "l"(b));
}

// =====================================================================
// Kernel 1: FPS. 1 block/cloud, 256 threads x 16 pts in registers.
// Packed f32x2 distance math (elementwise identical to scalar .rn ops),
// u64 (d2bits<<32 | ~idx) argmax keys, ONE barrier per iteration.
// =====================================================================
__global__ __launch_bounds__(256) void fps_kernel(
    const float* __restrict__ pos,
    float* __restrict__ out_centers,   // [NCTR,3]
    float* __restrict__ out_batch)     // [NCTR]
{
    const int b   = blockIdx.x;
    const int tid = threadIdx.x;
    const float* P = pos + (size_t)b * NPTS * 3;

    ull pxp[8], pyp[8], pzp[8];
    float dd[16];
#pragma unroll
    for (int q = 0; q < 8; q++) {
        int jA = tid + (q << 9);      // tid + 512q
        int jB = jA + 256;
        pxp[q] = pk2(P[3*jA],   P[3*jB]);
        pyp[q] = pk2(P[3*jA+1], P[3*jB+1]);
        pzp[q] = pk2(P[3*jA+2], P[3*jB+2]);
    }
#pragma unroll
    for (int i = 0; i < 16; i++) dd[i] = CUDART_INF_F;

    __shared__ ull s_wk[2][8];
    const int lane = tid & 31, wid = tid >> 5;

    int jwin = 0;
    for (int m = 0; m < MCTR; m++) {
        // all threads load current center (L1-resident, broadcast)
        float cx = P[3*jwin], cy = P[3*jwin+1], cz = P[3*jwin+2];
        if (tid == 0) {
            size_t o = (size_t)b * MCTR + m;
            out_centers[o*3+0] = cx;
            out_centers[o*3+1] = cy;
            out_centers[o*3+2] = cz;
            out_batch[o] = (float)b;
        }
        if (m == MCTR - 1) break;

        const ull ncx = pk2(-cx, -cx), ncy = pk2(-cy, -cy), ncz = pk2(-cz, -cz);
        float bd = -1.0f; int bj = 0;
#pragma unroll
        for (int q = 0; q < 8; q++) {
            ull dx = add2(pxp[q], ncx);            // == px - cx (exact)
            ull dy = add2(pyp[q], ncy);
            ull dz = add2(pzp[q], ncz);
            ull d2p = add2(add2(mul2(dx, dx), mul2(dy, dy)), mul2(dz, dz));
            float2 d = upk2(d2p);
            float nA = fminf(dd[2*q],   d.x);
            float nB = fminf(dd[2*q+1], d.y);
            dd[2*q] = nA; dd[2*q+1] = nB;
            // ascending j per thread, strict > keeps lowest index on ties
            if (nA > bd) { bd = nA; bj = tid + (q << 9); }
            if (nB > bd) { bd = nB; bj = tid + (q << 9) + 256; }
        }
        // key: larger d2 wins; equal d2 -> larger ~j = smaller j wins
        ull key = ((ull)__float_as_uint(bd) << 32) | (ull)(0xFFFFFFFFu - (unsigned)bj);
#pragma unroll
        for (int off = 16; off; off >>= 1) {
            ull ok = __shfl_down_sync(0xFFFFFFFFu, key, off);
            if (ok > key) key = ok;
        }
        if (lane == 0) s_wk[m & 1][wid] = key;
        __syncthreads();
        ull k0 = s_wk[m & 1][0];
#pragma unroll
        for (int w = 1; w < 8; w++) {
            ull kw = s_wk[m & 1][w];
            if (kw > k0) k0 = kw;
        }
        jwin = (int)(0xFFFFFFFFu - (unsigned)(k0 & 0xFFFFFFFFu));
    }
}

// =====================================================================
// Kernel 2: F1 = feat @ W1[0:64]  (per-point, center-independent part)
// =====================================================================
__global__ __launch_bounds__(64) void f1_kernel(
    const float* __restrict__ feat, const float* __restrict__ W1)
{
    __shared__ float sf[64][65];
    __shared__ float sw[64][64];
    const int p0  = blockIdx.x * 64;
    const int tid = threadIdx.x;

    for (int i = tid; i < 4096; i += 64) sw[i >> 6][i & 63] = W1[i];
    for (int i = tid; i < 4096; i += 64) {
        int p = i >> 6, c = i & 63;
        sf[p][c] = feat[(size_t)(p0 + p) * CIN + c];
    }
    __syncthreads();

    const int c = tid;
    for (int p = 0; p < 64; p += 4) {
        float a0 = 0.f, a1 = 0.f, a2 = 0.f, a3 = 0.f;
#pragma unroll
        for (int k = 0; k < 64; k++) {
            float w = sw[k][c];
            a0 += sf[p+0][k] * w;
            a1 += sf[p+1][k] * w;
            a2 += sf[p+2][k] * w;
            a3 += sf[p+3][k] * w;
        }
        g_F1[(size_t)(p0+p+0)*HID + c] = a0;
        g_F1[(size_t)(p0+p+1)*HID + c] = a1;
        g_F1[(size_t)(p0+p+2)*HID + c] = a2;
        g_F1[(size_t)(p0+p+3)*HID + c] = a3;
    }
}

// =====================================================================
// Kernel 3: exact K-nearest-in-ball selection per center.
// Radix-select rank-64; the per-pass bin scan is now a parallel
// 128-thread prefix scan (same (bin, k_lt) result as the serial walk).
// =====================================================================
__global__ __launch_bounds__(128) void select_kernel(
    const float* __restrict__ pos, const float* __restrict__ centers)
{
    const int cid = blockIdx.x;
    const int b   = cid >> 10;
    const int tid = threadIdx.x;
    const int lane = tid & 31, wid = tid >> 5;
    const float* P = pos + (size_t)b * NPTS * 3;

    __shared__ unsigned u[NPTS];
    __shared__ int hist[256];
    __shared__ int s_wsum[4];
    __shared__ int s_cnt, s_pos, s_bin, s_klt, s_eqn;
    __shared__ int s_eq[64];

    const float cx = centers[(size_t)cid*3+0];
    const float cy = centers[(size_t)cid*3+1];
    const float cz = centers[(size_t)cid*3+2];
    const float R2 = (float)(0.2 * 0.2);

    if (tid == 0) s_cnt = 0;
    __syncthreads();

    int lv = 0;
    for (int j = tid; j < NPTS; j += 128) {
        float dx = cx - P[3*j], dy = cy - P[3*j+1], dz = cz - P[3*j+2];
        float d2 = d2_nofma(dx, dy, dz);
        unsigned v = 0xFFFFFFFFu;
        if (d2 < R2) { v = __float_as_uint(d2); lv++; }
        u[j] = v;
    }
    if (lv) atomicAdd(&s_cnt, lv);
    __syncthreads();
    const int cnt = s_cnt;

    if (cnt <= KNBR) {
        if (tid == 0) s_pos = 0;
        __syncthreads();
        for (int j = tid; j < NPTS; j += 128)
            if (u[j] != 0xFFFFFFFFu) {
                int p = atomicAdd(&s_pos, 1);
                g_nbr[(size_t)cid*KNBR + p] = j;
            }
        __syncthreads();
        if (tid == 0) {
            for (int p = cnt; p < KNBR; p++) g_nbr[(size_t)cid*KNBR + p] = 0;
            g_cnt[cid] = cnt;
        }
        return;
    }

    unsigned pref = 0; int k = KNBR;
    for (int sh = 24; sh >= 0; sh -= 8) {
        for (int i = tid; i < 256; i += 128) hist[i] = 0;
        __syncthreads();
        unsigned hm = (sh == 24) ? 0u : (0xFFFFFFFFu << (sh + 8));
        for (int j = tid; j < NPTS; j += 128) {
            unsigned v = u[j];
            if (v != 0xFFFFFFFFu && (v & hm) == pref)
                atomicAdd(&hist[(v >> sh) & 255], 1);
        }
        __syncthreads();
        // parallel scan over 256 bins (thread owns bins 2t, 2t+1)
        {
            int h0 = hist[2*tid], h1 = hist[2*tid+1];
            int loc = h0 + h1;
            int inc = loc;
#pragma unroll
            for (int off = 1; off < 32; off <<= 1) {
                int t = __shfl_up_sync(0xFFFFFFFFu, inc, off);
                if (lane >= off) inc += t;
            }
            if (lane == 31) s_wsum[wid] = inc;
            __syncthreads();
            int woff = 0;
#pragma unroll
            for (int w = 0; w < 4; w++) if (w < wid) woff += s_wsum[w];
            int cumIncl   = inc + woff;           // cum through bin 2t+1
            int cumBefore = cumIncl - loc;        // cum before bin 2t
            // exactly one thread finds the first bin with cum >= k
            if (cumBefore < k && k <= cumBefore + h0) {
                s_bin = 2*tid;     s_klt = k - cumBefore;
            } else if (cumBefore + h0 < k && k <= cumIncl) {
                s_bin = 2*tid + 1; s_klt = k - cumBefore - h0;
            }
        }
        __syncthreads();
        pref |= ((unsigned)s_bin) << sh;
        k = s_klt;
        __syncthreads();
    }
    const unsigned T = pref;

    if (tid == 0) { s_pos = 0; s_eqn = 0; }
    __syncthreads();
    for (int j = tid; j < NPTS; j += 128) {
        unsigned v = u[j];
        if (v < T) {
            int p = atomicAdd(&s_pos, 1);
            g_nbr[(size_t)cid*KNBR + p] = j;
        } else if (v == T) {
            int e = atomicAdd(&s_eqn, 1);
            if (e < 64) s_eq[e] = j;
        }
    }
    __syncthreads();
    if (tid == 0) {
        int base = s_pos;
        int ne = s_eqn < 64 ? s_eqn : 64;
        for (int a = 1; a < ne; a++) {
            int key = s_eq[a], t2 = a - 1;
            while (t2 >= 0 && s_eq[t2] > key) { s_eq[t2+1] = s_eq[t2]; t2--; }
            s_eq[t2+1] = key;
        }
        for (int a = 0; a < k; a++) g_nbr[(size_t)cid*KNBR + base + a] = s_eq[a];
        g_cnt[cid] = KNBR;
    }
}

// =====================================================================
// Kernel 4: fused MLP + masked max. 2 centers/block, 128 threads.
// h1 stored k-major (conflict-free writes, LDS.128 broadcast reads for
// h2). h2 written back ROW-major as packed b64 (2-way conflict max) into
// the SAME buffer re-viewed [128][68]; h3 reads rows in 4-k LDS.128
// chunks. Col-paired f32x2 FFMA2 accumulators throughout.
// =====================================================================
#define HT_STRIDE 136     // ht[64][136]  (k-major view), 8704 floats
#define H2_STRIDE 68      // h2row[128][68] (row-major view, same buffer)

struct __align__(16) Mlp2Smem {
    float  buf[64 * HT_STRIDE];   // 34816 B, dual-view
    float  cmax[16][132];         // 8448 B
    float4 wb1[64];               // (W1pos0, W1pos1, W1pos2, b1)
    float  b2[64];
    float  b3[128];
    int    cnt[2];
};                                // ~45.2 KB static

__global__ __launch_bounds__(128) void mlp2_kernel(
    const float* __restrict__ pos, const float* __restrict__ centers,
    const float* __restrict__ W1, const float* __restrict__ b1,
    const float* __restrict__ W2, const float* __restrict__ b2,
    const float* __restrict__ W3, const float* __restrict__ b3,
    float* __restrict__ out)
{
    __shared__ Mlp2Smem S;

    const int c0  = blockIdx.x * 2;       // pair of centers; never crosses clouds
    const int b   = c0 >> 10;
    const int tid = threadIdx.x;

    // ---- stage weights/biases ----
    if (tid < 64) {
        S.wb1[tid] = make_float4(W1[4096 + tid], W1[4160 + tid], W1[4224 + tid], b1[tid]);
        S.b2[tid]  = b2[tid];
    }
    S.b3[tid] = b3[tid];
    if (tid < 2) S.cnt[tid] = g_cnt[c0 + tid];

    // ---- per-thread neighbor meta (n = tid, 128 neighbors = 2 centers) ----
    const int n      = tid;
    const int center = n >> 6;
    const int jl     = g_nbr[(size_t)c0 * KNBR + n];
    const float* Pp  = pos + ((size_t)b * NPTS + jl) * 3;
    const float* Cc  = centers + (size_t)(c0 + center) * 3;
    const float dp0 = Pp[0] - Cc[0];
    const float dp1 = Pp[1] - Cc[1];
    const float dp2 = Pp[2] - Cc[2];
    __syncthreads();

    float* ht = S.buf;   // k-major view: ht[k*HT_STRIDE + n]

    // ---- h1 = relu(F1[j] + dpos @ W1pos + b1), written k-major ----
    {
        const float4* F1p = (const float4*)&g_F1[((size_t)b * NPTS + jl) * HID];
#pragma unroll
        for (int q = 0; q < 16; q++) {
            float4 f = __ldg(F1p + q);
#pragma unroll
            for (int e = 0; e < 4; e++) {
                int k = 4*q + e;
                float4 w = S.wb1[k];                       // broadcast LDS.128
                float fe = (e == 0) ? f.x : (e == 1) ? f.y : (e == 2) ? f.z : f.w;
                float v  = fe + dp0*w.x + dp1*w.y + dp2*w.z + w.w;
                ht[k*HT_STRIDE + n] = fmaxf(v, 0.0f);     // lanes consecutive: 1 wf
            }
        }
    }
    __syncthreads();

    const int rg = tid >> 3, cg = tid & 7;
    const int r0 = rg * 8, cbase = cg * 8;

    // ---- h2 = relu(h1 @ W2 + b2): 128x64x64, 8x8 tiles, FFMA2 ----
    // acc[r][p] packs cols (cbase+2p, cbase+2p+1) of row r0+r
    ull acc[8][4];
    {
        ull binit[4];
#pragma unroll
        for (int p = 0; p < 4; p++) binit[p] = *(const ull*)&S.b2[cbase + 2*p];
#pragma unroll
        for (int r = 0; r < 8; r++)
#pragma unroll
            for (int p = 0; p < 4; p++) acc[r][p] = binit[p];
    }
#pragma unroll 4
    for (int k = 0; k < 64; k++) {
        float4 a0 = *(const float4*)(ht + k*HT_STRIDE + r0);
        float4 a1 = *(const float4*)(ht + k*HT_STRIDE + r0 + 4);
        ull aa[8];
        aa[0]=pk2(a0.x,a0.x); aa[1]=pk2(a0.y,a0.y); aa[2]=pk2(a0.z,a0.z); aa[3]=pk2(a0.w,a0.w);
        aa[4]=pk2(a1.x,a1.x); aa[5]=pk2(a1.y,a1.y); aa[6]=pk2(a1.z,a1.z); aa[7]=pk2(a1.w,a1.w);
        const float4* wr = (const float4*)(W2 + (size_t)k * 64 + cbase);
        float4 w0 = __ldg(wr), w1 = __ldg(wr + 1);
        ull wp[4];
        wp[0]=pk2(w0.x,w0.y); wp[1]=pk2(w0.z,w0.w); wp[2]=pk2(w1.x,w1.y); wp[3]=pk2(w1.z,w1.w);
#pragma unroll
        for (int r = 0; r < 8; r++)
#pragma unroll
            for (int p = 0; p < 4; p++) fma2(acc[r][p], aa[r], wp[p]);
    }
    __syncthreads();   // all ht reads done before buffer re-view

    // ---- relu + ROW-major writeback as packed b64 (h2row view) ----
    float* h2r = S.buf;  // row-major view: h2r[row*H2_STRIDE + ch]
#pragma unroll
    for (int r = 0; r < 8; r++)
#pragma unroll
        for (int p = 0; p < 4; p++) {
            float2 v = upk2(acc[r][p]);
            float2 rv = make_float2(fmaxf(v.x, 0.0f), fmaxf(v.y, 0.0f));
            *(float2*)(h2r + (r0 + r)*H2_STRIDE + cbase + 2*p) = rv;
        }
    __syncthreads();

    // ---- h3 = relu(h2 @ W3 + b3): 128x128x64 in two 64-col halves ----
    const int cn = S.cnt[rg >> 3];     // rows of this rg all belong to one center
#pragma unroll
    for (int half = 0; half < 2; half++) {
        ull acc3[8][4];
        {
            ull binit[4];
#pragma unroll
            for (int p = 0; p < 4; p++)
                binit[p] = *(const ull*)&S.b3[half*64 + cbase + 2*p];
#pragma unroll
            for (int r = 0; r < 8; r++)
#pragma unroll
                for (int p = 0; p < 4; p++) acc3[r][p] = binit[p];
        }
#pragma unroll 2
        for (int kc = 0; kc < 16; kc++) {        // chunks of 4 k's
            float ar[8][4];
#pragma unroll
            for (int r = 0; r < 8; r++)
                *(float4*)ar[r] = *(const float4*)(h2r + (r0 + r)*H2_STRIDE + kc*4);
#pragma unroll
            for (int e = 0; e < 4; e++) {
                int k = kc*4 + e;
                ull aa[8];
#pragma unroll
                for (int r = 0; r < 8; r++) aa[r] = pk2(ar[r][e], ar[r][e]);
                const float4* wr = (const float4*)(W3 + (size_t)k * OUTC + half*64 + cbase);
                float4 w0 = __ldg(wr), w1 = __ldg(wr + 1);
                ull wp[4];
                wp[0]=pk2(w0.x,w0.y); wp[1]=pk2(w0.z,w0.w); wp[2]=pk2(w1.x,w1.y); wp[3]=pk2(w1.z,w1.w);
#pragma unroll
                for (int r = 0; r < 8; r++)
#pragma unroll
                    for (int p = 0; p < 4; p++) fma2(acc3[r][p], aa[r], wp[p]);
            }
        }
        // masked relu-max over this thread's 8 rows
        float cm[8];
#pragma unroll
        for (int c = 0; c < 8; c++) cm[c] = -CUDART_INF_F;
#pragma unroll
        for (int r = 0; r < 8; r++) {
            if (((r0 + r) & 63) < cn) {
#pragma unroll
                for (int p = 0; p < 4; p++) {
                    float2 v = upk2(acc3[r][p]);
                    cm[2*p]     = fmaxf(cm[2*p],     fmaxf(v.x, 0.0f));
                    cm[2*p + 1] = fmaxf(cm[2*p + 1], fmaxf(v.y, 0.0f));
                }
            }
        }
#pragma unroll
        for (int c = 0; c < 8; c++) S.cmax[rg][half*64 + cbase + c] = cm[c];
    }
    __syncthreads();

    // ---- final per-center reduction over rowgroups ----
    float v0 = -CUDART_INF_F, v1 = -CUDART_INF_F;
#pragma unroll
    for (int g = 0; g < 8; g++) {
        v0 = fmaxf(v0, S.cmax[g][tid]);
        v1 = fmaxf(v1, S.cmax[8 + g][tid]);
    }
    out[(size_t)c0 * OUTC + tid]       = v0;
    out[(size_t)(c0 + 1) * OUTC + tid] = v1;
}

// =====================================================================
extern "C" void kernel_launch(void* const* d_in, const int* in_sizes, int n_in,
                              void* d_out, int out_size)
{
    const float *xyz = nullptr, *point = nullptr;
    const float *W1 = nullptr, *b1 = nullptr, *W2 = nullptr, *b2 = nullptr;
    const float *W3 = nullptr, *b3 = nullptr;
    for (int i = 0; i < n_in; i++) {
        switch (in_sizes[i]) {
            case 4194304: xyz   = (const float*)d_in[i]; break;  // 65536*64
            case 196608:  point = (const float*)d_in[i]; break;  // 65536*3
            case 4288:    W1    = (const float*)d_in[i]; break;  // 67*64
            case 4096:    W2    = (const float*)d_in[i]; break;  // 64*64
            case 8192:    W3    = (const float*)d_in[i]; break;  // 64*128
            case 128:     b3    = (const float*)d_in[i]; break;
            case 64:      if (!b1) b1 = (const float*)d_in[i];
                          else     b2 = (const float*)d_in[i];   break;
            default: break;  // batch (65536), num_samples (1)
        }
    }

    float* out      = (float*)d_out;
    float* cenout   = out + (size_t)NCTR * OUTC;
    float* batchout = cenout + (size_t)NCTR * 3;

    fps_kernel<<<BCL, 256>>>(point, cenout, batchout);
    f1_kernel<<<(BCL * NPTS) / 64, 64>>>(xyz, W1);
    select_kernel<<<NCTR, 128>>>(point, cenout);
    mlp2_kernel<<<NCTR / 2, 128>>>(point, cenout, W1, b1, W2, b2, W3, b3, out);
}

// round 10
// speedup vs baseline: 1.9599x; 1.0170x over previous
#include <cuda_runtime.h>
#include <math_constants.h>
#include <cstdint>

#define BCL   16
#define NPTS  4096
#define MCTR  1024
#define CIN   64
#define HID   64
#define OUTC  128
#define KNBR  64
#define NCTR  (BCL*MCTR)

typedef unsigned long long ull;

// ---------------- device scratch (no allocs allowed) ----------------
__device__ float g_F1[(size_t)BCL*NPTS*HID];   // 16 MB: feat @ W1[0:64]
__device__ int   g_nbr[(size_t)NCTR*KNBR];
__device__ int   g_cnt[NCTR];

// d2 with NO fma contraction, left-assoc — must match XLA's sum((a-b)**2, -1)
__device__ __forceinline__ float d2_nofma(float dx, float dy, float dz) {
    return __fadd_rn(__fadd_rn(__fmul_rn(dx, dx), __fmul_rn(dy, dy)), __fmul_rn(dz, dz));
}

// ---------------- packed f32x2 helpers (sm_103a) ----------------
__device__ __forceinline__ ull pk2(float lo, float hi) {
    ull r;
    asm("mov.b64 %0, {%1, %2};" : "=l"(r)
        : "r"(__float_as_uint(lo)), "r"(__float_as_uint(hi)));
    return r;
}
__device__ __forceinline__ float2 upk2(ull v) {
    unsigned lo, hi;
    asm("mov.b64 {%0, %1}, %2;" : "=r"(lo), "=r"(hi) : "l"(v));
    return make_float2(__uint_as_float(lo), __uint_as_float(hi));
}
__device__ __forceinline__ ull mul2(ull a, ull b) {
    ull r; asm("mul.rn.f32x2 %0, %1, %2;" : "=l"(r) : "l"(a), "l"(b)); return r;
}
__device__ __forceinline__ ull add2(ull a, ull b) {
    ull r; asm("add.rn.f32x2 %0, %1, %2;" : "=l"(r) : "l"(a), "l"(b)); return r;
}
__device__ __forceinline__ void fma2(ull& d, ull a, ull b) {
    asm("fma.rn.f32x2 %0, %1, %2, %0;" : "+l"(d) : "l"(a), "l"(b));
}

// =====================================================================
// Kernel 1: FPS. 1 block/cloud, 256 threads x 16 pts in registers.
// (unchanged from R9 — bit-exact, rel_err 0.0)
// =====================================================================
__global__ __launch_bounds__(256) void fps_kernel(
    const float* __restrict__ pos,
    float* __restrict__ out_centers,   // [NCTR,3]
    float* __restrict__ out_batch)     // [NCTR]
{
    const int b   = blockIdx.x;
    const int tid = threadIdx.x;
    const float* P = pos + (size_t)b * NPTS * 3;

    ull pxp[8], pyp[8], pzp[8];
    float dd[16];
#pragma unroll
    for (int q = 0; q < 8; q++) {
        int jA = tid + (q << 9);      // tid + 512q
        int jB = jA + 256;
        pxp[q] = pk2(P[3*jA],   P[3*jB]);
        pyp[q] = pk2(P[3*jA+1], P[3*jB+1]);
        pzp[q] = pk2(P[3*jA+2], P[3*jB+2]);
    }
#pragma unroll
    for (int i = 0; i < 16; i++) dd[i] = CUDART_INF_F;

    __shared__ ull s_wk[2][8];
    const int lane = tid & 31, wid = tid >> 5;

    int jwin = 0;
    for (int m = 0; m < MCTR; m++) {
        float cx = P[3*jwin], cy = P[3*jwin+1], cz = P[3*jwin+2];
        if (tid == 0) {
            size_t o = (size_t)b * MCTR + m;
            out_centers[o*3+0] = cx;
            out_centers[o*3+1] = cy;
            out_centers[o*3+2] = cz;
            out_batch[o] = (float)b;
        }
        if (m == MCTR - 1) break;

        const ull ncx = pk2(-cx, -cx), ncy = pk2(-cy, -cy), ncz = pk2(-cz, -cz);
        float bd = -1.0f; int bj = 0;
#pragma unroll
        for (int q = 0; q < 8; q++) {
            ull dx = add2(pxp[q], ncx);            // == px - cx (exact)
            ull dy = add2(pyp[q], ncy);
            ull dz = add2(pzp[q], ncz);
            ull d2p = add2(add2(mul2(dx, dx), mul2(dy, dy)), mul2(dz, dz));
            float2 d = upk2(d2p);
            float nA = fminf(dd[2*q],   d.x);
            float nB = fminf(dd[2*q+1], d.y);
            dd[2*q] = nA; dd[2*q+1] = nB;
            if (nA > bd) { bd = nA; bj = tid + (q << 9); }
            if (nB > bd) { bd = nB; bj = tid + (q << 9) + 256; }
        }
        ull key = ((ull)__float_as_uint(bd) << 32) | (ull)(0xFFFFFFFFu - (unsigned)bj);
#pragma unroll
        for (int off = 16; off; off >>= 1) {
            ull ok = __shfl_down_sync(0xFFFFFFFFu, key, off);
            if (ok > key) key = ok;
        }
        if (lane == 0) s_wk[m & 1][wid] = key;
        __syncthreads();
        ull k0 = s_wk[m & 1][0];
#pragma unroll
        for (int w = 1; w < 8; w++) {
            ull kw = s_wk[m & 1][w];
            if (kw > k0) k0 = kw;
        }
        jwin = (int)(0xFFFFFFFFu - (unsigned)(k0 & 0xFFFFFFFFu));
    }
}

// =====================================================================
// Kernel 2: F1 = feat @ W1[0:64]  (unchanged)
// =====================================================================
__global__ __launch_bounds__(64) void f1_kernel(
    const float* __restrict__ feat, const float* __restrict__ W1)
{
    __shared__ float sf[64][65];
    __shared__ float sw[64][64];
    const int p0  = blockIdx.x * 64;
    const int tid = threadIdx.x;

    for (int i = tid; i < 4096; i += 64) sw[i >> 6][i & 63] = W1[i];
    for (int i = tid; i < 4096; i += 64) {
        int p = i >> 6, c = i & 63;
        sf[p][c] = feat[(size_t)(p0 + p) * CIN + c];
    }
    __syncthreads();

    const int c = tid;
    for (int p = 0; p < 64; p += 4) {
        float a0 = 0.f, a1 = 0.f, a2 = 0.f, a3 = 0.f;
#pragma unroll
        for (int k = 0; k < 64; k++) {
            float w = sw[k][c];
            a0 += sf[p+0][k] * w;
            a1 += sf[p+1][k] * w;
            a2 += sf[p+2][k] * w;
            a3 += sf[p+3][k] * w;
        }
        g_F1[(size_t)(p0+p+0)*HID + c] = a0;
        g_F1[(size_t)(p0+p+1)*HID + c] = a1;
        g_F1[(size_t)(p0+p+2)*HID + c] = a2;
        g_F1[(size_t)(p0+p+3)*HID + c] = a3;
    }
}

// =====================================================================
// Kernel 3: exact K-nearest-in-ball selection per center (unchanged).
// =====================================================================
__global__ __launch_bounds__(128) void select_kernel(
    const float* __restrict__ pos, const float* __restrict__ centers)
{
    const int cid = blockIdx.x;
    const int b   = cid >> 10;
    const int tid = threadIdx.x;
    const int lane = tid & 31, wid = tid >> 5;
    const float* P = pos + (size_t)b * NPTS * 3;

    __shared__ unsigned u[NPTS];
    __shared__ int hist[256];
    __shared__ int s_wsum[4];
    __shared__ int s_cnt, s_pos, s_bin, s_klt, s_eqn;
    __shared__ int s_eq[64];

    const float cx = centers[(size_t)cid*3+0];
    const float cy = centers[(size_t)cid*3+1];
    const float cz = centers[(size_t)cid*3+2];
    const float R2 = (float)(0.2 * 0.2);

    if (tid == 0) s_cnt = 0;
    __syncthreads();

    int lv = 0;
    for (int j = tid; j < NPTS; j += 128) {
        float dx = cx - P[3*j], dy = cy - P[3*j+1], dz = cz - P[3*j+2];
        float d2 = d2_nofma(dx, dy, dz);
        unsigned v = 0xFFFFFFFFu;
        if (d2 < R2) { v = __float_as_uint(d2); lv++; }
        u[j] = v;
    }
    if (lv) atomicAdd(&s_cnt, lv);
    __syncthreads();
    const int cnt = s_cnt;

    if (cnt <= KNBR) {
        if (tid == 0) s_pos = 0;
        __syncthreads();
        for (int j = tid; j < NPTS; j += 128)
            if (u[j] != 0xFFFFFFFFu) {
                int p = atomicAdd(&s_pos, 1);
                g_nbr[(size_t)cid*KNBR + p] = j;
            }
        __syncthreads();
        if (tid == 0) {
            for (int p = cnt; p < KNBR; p++) g_nbr[(size_t)cid*KNBR + p] = 0;
            g_cnt[cid] = cnt;
        }
        return;
    }

    unsigned pref = 0; int k = KNBR;
    for (int sh = 24; sh >= 0; sh -= 8) {
        for (int i = tid; i < 256; i += 128) hist[i] = 0;
        __syncthreads();
        unsigned hm = (sh == 24) ? 0u : (0xFFFFFFFFu << (sh + 8));
        for (int j = tid; j < NPTS; j += 128) {
            unsigned v = u[j];
            if (v != 0xFFFFFFFFu && (v & hm) == pref)
                atomicAdd(&hist[(v >> sh) & 255], 1);
        }
        __syncthreads();
        {
            int h0 = hist[2*tid], h1 = hist[2*tid+1];
            int loc = h0 + h1;
            int inc = loc;
#pragma unroll
            for (int off = 1; off < 32; off <<= 1) {
                int t = __shfl_up_sync(0xFFFFFFFFu, inc, off);
                if (lane >= off) inc += t;
            }
            if (lane == 31) s_wsum[wid] = inc;
            __syncthreads();
            int woff = 0;
#pragma unroll
            for (int w = 0; w < 4; w++) if (w < wid) woff += s_wsum[w];
            int cumIncl   = inc + woff;
            int cumBefore = cumIncl - loc;
            if (cumBefore < k && k <= cumBefore + h0) {
                s_bin = 2*tid;     s_klt = k - cumBefore;
            } else if (cumBefore + h0 < k && k <= cumIncl) {
                s_bin = 2*tid + 1; s_klt = k - cumBefore - h0;
            }
        }
        __syncthreads();
        pref |= ((unsigned)s_bin) << sh;
        k = s_klt;
        __syncthreads();
    }
    const unsigned T = pref;

    if (tid == 0) { s_pos = 0; s_eqn = 0; }
    __syncthreads();
    for (int j = tid; j < NPTS; j += 128) {
        unsigned v = u[j];
        if (v < T) {
            int p = atomicAdd(&s_pos, 1);
            g_nbr[(size_t)cid*KNBR + p] = j;
        } else if (v == T) {
            int e = atomicAdd(&s_eqn, 1);
            if (e < 64) s_eq[e] = j;
        }
    }
    __syncthreads();
    if (tid == 0) {
        int base = s_pos;
        int ne = s_eqn < 64 ? s_eqn : 64;
        for (int a = 1; a < ne; a++) {
            int key = s_eq[a], t2 = a - 1;
            while (t2 >= 0 && s_eq[t2] > key) { s_eq[t2+1] = s_eq[t2]; t2--; }
            s_eq[t2+1] = key;
        }
        for (int a = 0; a < k; a++) g_nbr[(size_t)cid*KNBR + base + a] = s_eq[a];
        g_cnt[cid] = KNBR;
    }
}

// =====================================================================
// Kernel 4: fused MLP + masked max. 2 centers/block, 128 threads.
// h1 k-major (conflict-free). h2 written back row-major with a 16B-chunk
// XOR swizzle (chunk slot = c4 ^ (row>>3)) -> h3 LDS.128 reads are
// conflict-free across the warp's rg lanes. Weights loaded directly as
// packed ulonglong2 (no repack movs). FFMA2 accumulators throughout.
// =====================================================================
#define HT_STRIDE 136     // ht[64][136]  (k-major view), 8704 floats
#define H2_STRIDE 68      // h2row[128][68] (row-major swizzled view) = 4*17

struct __align__(16) Mlp2Smem {
    float  buf[64 * HT_STRIDE];   // 34816 B, dual-view
    float  cmax[16][132];         // 8448 B
    float4 wb1[64];               // (W1pos0, W1pos1, W1pos2, b1)
    float  b2[64];
    float  b3[128];
    int    cnt[2];
};                                // ~45.2 KB static

__global__ __launch_bounds__(128) void mlp2_kernel(
    const float* __restrict__ pos, const float* __restrict__ centers,
    const float* __restrict__ W1, const float* __restrict__ b1,
    const float* __restrict__ W2, const float* __restrict__ b2,
    const float* __restrict__ W3, const float* __restrict__ b3,
    float* __restrict__ out)
{
    __shared__ Mlp2Smem S;

    const int c0  = blockIdx.x * 2;       // pair of centers; never crosses clouds
    const int b   = c0 >> 10;
    const int tid = threadIdx.x;

    // ---- stage weights/biases ----
    if (tid < 64) {
        S.wb1[tid] = make_float4(W1[4096 + tid], W1[4160 + tid], W1[4224 + tid], b1[tid]);
        S.b2[tid]  = b2[tid];
    }
    S.b3[tid] = b3[tid];
    if (tid < 2) S.cnt[tid] = g_cnt[c0 + tid];

    // ---- per-thread neighbor meta (n = tid, 128 neighbors = 2 centers) ----
    const int n      = tid;
    const int center = n >> 6;
    const int jl     = g_nbr[(size_t)c0 * KNBR + n];
    const float* Pp  = pos + ((size_t)b * NPTS + jl) * 3;
    const float* Cc  = centers + (size_t)(c0 + center) * 3;
    const float dp0 = Pp[0] - Cc[0];
    const float dp1 = Pp[1] - Cc[1];
    const float dp2 = Pp[2] - Cc[2];
    __syncthreads();

    float* ht = S.buf;   // k-major view: ht[k*HT_STRIDE + n]

    // ---- h1 = relu(F1[j] + dpos @ W1pos + b1), written k-major ----
    {
        const float4* F1p = (const float4*)&g_F1[((size_t)b * NPTS + jl) * HID];
#pragma unroll
        for (int q = 0; q < 16; q++) {
            float4 f = __ldg(F1p + q);
#pragma unroll
            for (int e = 0; e < 4; e++) {
                int k = 4*q + e;
                float4 w = S.wb1[k];                       // broadcast LDS.128
                float fe = (e == 0) ? f.x : (e == 1) ? f.y : (e == 2) ? f.z : f.w;
                float v  = fe + dp0*w.x + dp1*w.y + dp2*w.z + w.w;
                ht[k*HT_STRIDE + n] = fmaxf(v, 0.0f);     // lanes consecutive: 1 wf
            }
        }
    }
    __syncthreads();

    const int rg = tid >> 3, cg = tid & 7;
    const int r0 = rg * 8, cbase = cg * 8;
    const int rsw = rg & 7;                  // row>>3 for this thread's rows

    // ---- h2 = relu(h1 @ W2 + b2): 128x64x64, 8x8 tiles, FFMA2 ----
    ull acc[8][4];
    {
        ull binit[4];
#pragma unroll
        for (int p = 0; p < 4; p++) binit[p] = *(const ull*)&S.b2[cbase + 2*p];
#pragma unroll
        for (int r = 0; r < 8; r++)
#pragma unroll
            for (int p = 0; p < 4; p++) acc[r][p] = binit[p];
    }
#pragma unroll 4
    for (int k = 0; k < 64; k++) {
        float4 a0 = *(const float4*)(ht + k*HT_STRIDE + r0);
        float4 a1 = *(const float4*)(ht + k*HT_STRIDE + r0 + 4);
        ull aa[8];
        aa[0]=pk2(a0.x,a0.x); aa[1]=pk2(a0.y,a0.y); aa[2]=pk2(a0.z,a0.z); aa[3]=pk2(a0.w,a0.w);
        aa[4]=pk2(a1.x,a1.x); aa[5]=pk2(a1.y,a1.y); aa[6]=pk2(a1.z,a1.z); aa[7]=pk2(a1.w,a1.w);
        // weights: adjacent float pairs ARE the packed operands — load directly
        const ulonglong2* wr = (const ulonglong2*)(W2 + (size_t)k * 64 + cbase);
        ulonglong2 wv = __ldg(wr);
        ull wp[4]; wp[0] = wv.x; wp[1] = wv.y;
        ulonglong2 wv2 = __ldg(wr + 1);
        wp[2] = wv2.x; wp[3] = wv2.y;
#pragma unroll
        for (int r = 0; r < 8; r++)
#pragma unroll
            for (int p = 0; p < 4; p++) fma2(acc[r][p], aa[r], wp[p]);
    }
    __syncthreads();   // all ht reads done before buffer re-view

    // ---- relu + swizzled row-major writeback (h2row view) ----
    // value (row, ch) -> word  row*68 + ((ch>>2) ^ (row>>3))*4 + (ch&3)
    float* h2r = S.buf;
#pragma unroll
    for (int r = 0; r < 8; r++) {
        float* rowp = h2r + (r0 + r) * H2_STRIDE;
#pragma unroll
        for (int p = 0; p < 4; p++) {
            float2 v = upk2(acc[r][p]);
            float2 rv = make_float2(fmaxf(v.x, 0.0f), fmaxf(v.y, 0.0f));
            int c4   = (cbase >> 2) + (p >> 1);      // 16B chunk of channel pair
            int slot = c4 ^ rsw;
            *(float2*)(rowp + (slot << 2) + ((2*p) & 3)) = rv;
        }
    }
    __syncthreads();

    // ---- h3 = relu(h2 @ W3 + b3): 128x128x64 in two 64-col halves ----
    const int cn = S.cnt[rg >> 3];     // rows of this rg all belong to one center
#pragma unroll
    for (int half = 0; half < 2; half++) {
        ull acc3[8][4];
        {
            ull binit[4];
#pragma unroll
            for (int p = 0; p < 4; p++)
                binit[p] = *(const ull*)&S.b3[half*64 + cbase + 2*p];
#pragma unroll
            for (int r = 0; r < 8; r++)
#pragma unroll
                for (int p = 0; p < 4; p++) acc3[r][p] = binit[p];
        }
#pragma unroll 2
        for (int kc = 0; kc < 16; kc++) {        // chunks of 4 k's
            float ar[8][4];
#pragma unroll
            for (int r = 0; r < 8; r++) {
                int slot = kc ^ rsw;             // de-swizzle (row>>3 == rsw)
                *(float4*)ar[r] = *(const float4*)(h2r + (r0 + r)*H2_STRIDE + (slot << 2));
            }
#pragma unroll
            for (int e = 0; e < 4; e++) {
                int k = kc*4 + e;
                ull aa[8];
#pragma unroll
                for (int r = 0; r < 8; r++) aa[r] = pk2(ar[r][e], ar[r][e]);
                const ulonglong2* wr = (const ulonglong2*)(W3 + (size_t)k * OUTC + half*64 + cbase);
                ulonglong2 wv = __ldg(wr);
                ull wp[4]; wp[0] = wv.x; wp[1] = wv.y;
                ulonglong2 wv2 = __ldg(wr + 1);
                wp[2] = wv2.x; wp[3] = wv2.y;
#pragma unroll
                for (int r = 0; r < 8; r++)
#pragma unroll
                    for (int p = 0; p < 4; p++) fma2(acc3[r][p], aa[r], wp[p]);
            }
        }
        // masked relu-max over this thread's 8 rows
        float cm[8];
#pragma unroll
        for (int c = 0; c < 8; c++) cm[c] = -CUDART_INF_F;
#pragma unroll
        for (int r = 0; r < 8; r++) {
            if (((r0 + r) & 63) < cn) {
#pragma unroll
                for (int p = 0; p < 4; p++) {
                    float2 v = upk2(acc3[r][p]);
                    cm[2*p]     = fmaxf(cm[2*p],     fmaxf(v.x, 0.0f));
                    cm[2*p + 1] = fmaxf(cm[2*p + 1], fmaxf(v.y, 0.0f));
                }
            }
        }
#pragma unroll
        for (int c = 0; c < 8; c++) S.cmax[rg][half*64 + cbase + c] = cm[c];
    }
    __syncthreads();

    // ---- final per-center reduction over rowgroups ----
    float v0 = -CUDART_INF_F, v1 = -CUDART_INF_F;
#pragma unroll
    for (int g = 0; g < 8; g++) {
        v0 = fmaxf(v0, S.cmax[g][tid]);
        v1 = fmaxf(v1, S.cmax[8 + g][tid]);
    }
    out[(size_t)c0 * OUTC + tid]       = v0;
    out[(size_t)(c0 + 1) * OUTC + tid] = v1;
}

// =====================================================================
extern "C" void kernel_launch(void* const* d_in, const int* in_sizes, int n_in,
                              void* d_out, int out_size)
{
    const float *xyz = nullptr, *point = nullptr;
    const float *W1 = nullptr, *b1 = nullptr, *W2 = nullptr, *b2 = nullptr;
    const float *W3 = nullptr, *b3 = nullptr;
    for (int i = 0; i < n_in; i++) {
        switch (in_sizes[i]) {
            case 4194304: xyz   = (const float*)d_in[i]; break;  // 65536*64
            case 196608:  point = (const float*)d_in[i]; break;  // 65536*3
            case 4288:    W1    = (const float*)d_in[i]; break;  // 67*64
            case 4096:    W2    = (const float*)d_in[i]; break;  // 64*64
            case 8192:    W3    = (const float*)d_in[i]; break;  // 64*128
            case 128:     b3    = (const float*)d_in[i]; break;
            case 64:      if (!b1) b1 = (const float*)d_in[i];
                          else     b2 = (const float*)d_in[i];   break;
            default: break;  // batch (65536), num_samples (1)
        }
    }

    float* out      = (float*)d_out;
    float* cenout   = out + (size_t)NCTR * OUTC;
    float* batchout = cenout + (size_t)NCTR * 3;

    fps_kernel<<<BCL, 256>>>(point, cenout, batchout);
    f1_kernel<<<(BCL * NPTS) / 64, 64>>>(xyz, W1);
    select_kernel<<<NCTR, 128>>>(point, cenout);
    mlp2_kernel<<<NCTR / 2, 128>>>(point, cenout, W1, b1, W2, b2, W3, b3, out);
}